// round 11
// baseline (speedup 1.0000x reference)
#include <cuda_runtime.h>
#include <cuda_fp16.h>
#include <cstdint>

// ---------------------------------------------------------------------------
// C[8192,4096] = A[8192,4096] * W[4096,4096]^T  (fp32 in/out)
// R11: fp16 m16n8k16 GEMM. vs R10: intra-iteration fragment software
// pipelining (ldsm of ks+1 overlaps mma of ks) to close the ~38% tensor-pipe
// idle caused by LDSM->HMMA dependency gaps.
// BM=128, BN=128, BK=64, 256 thr x 2 CTAs/SM, warp 32x64, 3-stage cp.async.
// ---------------------------------------------------------------------------

#define MTOT 8192
#define KDIM 4096
#define NDIM 4096

#define BM 128
#define BN 128
#define BK 64
#define KITERS (KDIM / BK)        // 64
#define STAGES 3

// fp16 smem rows: 64 fp16 = 128B data + 16B pad = 144B stride.
#define ROWB 144
#define A_OFF 0
#define B_OFF (BM * ROWB)                  // 18432
#define STAGE_BYTES ((BM + BN) * ROWB)     // 36864
#define SMEM_TOTAL (STAGES * STAGE_BYTES)  // 110592  (x2 CTAs = 221184/SM)

// fp16 scratch copies (device globals: allowed, no allocation)
__device__ __half g_Ah[(size_t)MTOT * KDIM];
__device__ __half g_Wh[(size_t)NDIM * KDIM];

// ------------------------------- helpers -----------------------------------

__device__ __forceinline__ uint32_t smem_u32(const void* p) {
    uint32_t a;
    asm("{ .reg .u64 t; cvta.to.shared.u64 t, %1; cvt.u32.u64 %0, t; }"
        : "=r"(a) : "l"(p));
    return a;
}

__device__ __forceinline__ void cp_async16(uint32_t dst, const void* src) {
    asm volatile("cp.async.cg.shared.global [%0], [%1], 16;\n"
                 :: "r"(dst), "l"(src) : "memory");
}
__device__ __forceinline__ void cp_commit() {
    asm volatile("cp.async.commit_group;\n" ::: "memory");
}
__device__ __forceinline__ void cp_wait1() {
    asm volatile("cp.async.wait_group 1;\n" ::: "memory");
}

__device__ __forceinline__ void ldsm_x4(uint32_t& r0, uint32_t& r1,
                                        uint32_t& r2, uint32_t& r3,
                                        uint32_t addr) {
    asm volatile("ldmatrix.sync.aligned.m8n8.x4.shared.b16 {%0,%1,%2,%3}, [%4];"
                 : "=r"(r0), "=r"(r1), "=r"(r2), "=r"(r3) : "r"(addr));
}

__device__ __forceinline__ void mma_f16(float* c, const uint32_t* a,
                                        const uint32_t* b) {
    asm volatile(
        "mma.sync.aligned.m16n8k16.row.col.f32.f16.f16.f32 "
        "{%0,%1,%2,%3}, {%4,%5,%6,%7}, {%8,%9}, {%0,%1,%2,%3};"
        : "+f"(c[0]), "+f"(c[1]), "+f"(c[2]), "+f"(c[3])
        : "r"(a[0]), "r"(a[1]), "r"(a[2]), "r"(a[3]),
          "r"(b[0]), "r"(b[1]));
}

// ------------------------------- prepass ------------------------------------

__global__ void __launch_bounds__(256) prepass_kernel(const float* __restrict__ A,
                                                      const float* __restrict__ W) {
    const long long nA = (long long)MTOT * KDIM / 4;
    const long long nW = (long long)NDIM * KDIM / 4;
    const long long stride = (long long)gridDim.x * blockDim.x;
    for (long long i = (long long)blockIdx.x * blockDim.x + threadIdx.x;
         i < nA + nW; i += stride) {
        const float4* src;
        __half* dst;
        long long j;
        if (i < nA) { src = (const float4*)A; dst = g_Ah; j = i; }
        else        { src = (const float4*)W; dst = g_Wh; j = i - nA; }
        float4 v = src[j];
        __half2* p = (__half2*)(dst + 4 * j);
        p[0] = __floats2half2_rn(v.x, v.y);
        p[1] = __floats2half2_rn(v.z, v.w);
    }
}

// ------------------------------- GEMM ---------------------------------------

__global__ void __launch_bounds__(256, 2) gemm_kernel(float* __restrict__ out) {
    extern __shared__ char smem[];
    const uint32_t sbase = smem_u32(smem);
    const int tid = threadIdx.x;
    const int lane = tid & 31;
    const int wid = tid >> 5;
    const int warp_m = wid & 3;       // 0..3 -> 32-row strip
    const int warp_n = wid >> 2;      // 0..1 -> 64-col strip
    const int grp = lane >> 2;
    const int tig = lane & 3;

    const int m_base = blockIdx.y * BM;
    const int n_base = blockIdx.x * BN;

    // --- ldmatrix per-lane base addresses (stage 0) ---
    const int lj = lane >> 3;         // matrix index 0..3
    const int lr = lane & 7;          // row within matrix
    const uint32_t a_lane = sbase + A_OFF
        + (uint32_t)((warp_m * 32 + (lj & 1) * 8 + lr) * ROWB + (lj >> 1) * 16);
    const uint32_t b_lane = sbase + B_OFF
        + (uint32_t)((warp_n * 64 + (lj >> 1) * 8 + lr) * ROWB + (lj & 1) * 16);

    float acc[2][8][4];
    #pragma unroll
    for (int t = 0; t < 2; t++)
        #pragma unroll
        for (int j = 0; j < 8; j++)
            #pragma unroll
            for (int q = 0; q < 4; q++)
                acc[t][j][q] = 0.0f;

    auto produce = [&](int stage, int kb) {
        char* st = smem + stage * STAGE_BYTES;
        const size_t kel = (size_t)kb * BK;
        #pragma unroll
        for (int j = 0; j < 4; j++) {
            const int c = tid + 256 * j;     // 0..1023
            const int r = c >> 3, ch = c & 7;
            cp_async16(smem_u32(st + A_OFF + r * ROWB + ch * 16),
                       g_Ah + (size_t)(m_base + r) * KDIM + kel + ch * 8);
        }
        #pragma unroll
        for (int j = 0; j < 4; j++) {
            const int c = tid + 256 * j;     // 0..1023
            const int r = c >> 3, ch = c & 7;
            cp_async16(smem_u32(st + B_OFF + r * ROWB + ch * 16),
                       g_Wh + (size_t)(n_base + r) * KDIM + kel + ch * 8);
        }
    };

    // prologue: fill 2 of 3 stages
    produce(0, 0); cp_commit();
    produce(1, 1); cp_commit();

    // fragment double buffers
    uint32_t af[2][2][4], bf[2][8][2];

    int stage = 0;
    for (int it = 0; it < KITERS; ++it) {
        cp_wait1();
        __syncthreads();

        if (it + 2 < KITERS) {
            int ps = stage + 2; if (ps >= STAGES) ps -= STAGES;
            produce(ps, it + 2);
        }
        cp_commit();

        const uint32_t so = (uint32_t)(stage * STAGE_BYTES);

        // load ks=0 fragments into buffer 0
        #pragma unroll
        for (int t = 0; t < 2; t++)
            ldsm_x4(af[0][t][0], af[0][t][1], af[0][t][2], af[0][t][3],
                    a_lane + so + (uint32_t)(t * 16 * ROWB));
        #pragma unroll
        for (int p = 0; p < 4; p++)
            ldsm_x4(bf[0][2 * p][0], bf[0][2 * p][1],
                    bf[0][2 * p + 1][0], bf[0][2 * p + 1][1],
                    b_lane + so + (uint32_t)(p * 16 * ROWB));

        #pragma unroll
        for (int ks = 0; ks < 4; ks++) {      // 4 x k16 = BK 64
            const int cur = ks & 1;
            const int nxt = cur ^ 1;
            if (ks < 3) {                     // prefetch ks+1 fragments
                const uint32_t koff = so + (uint32_t)((ks + 1) * 32);
                #pragma unroll
                for (int t = 0; t < 2; t++)
                    ldsm_x4(af[nxt][t][0], af[nxt][t][1], af[nxt][t][2], af[nxt][t][3],
                            a_lane + koff + (uint32_t)(t * 16 * ROWB));
                #pragma unroll
                for (int p = 0; p < 4; p++)
                    ldsm_x4(bf[nxt][2 * p][0], bf[nxt][2 * p][1],
                            bf[nxt][2 * p + 1][0], bf[nxt][2 * p + 1][1],
                            b_lane + koff + (uint32_t)(p * 16 * ROWB));
            }
            #pragma unroll
            for (int t = 0; t < 2; t++)
                #pragma unroll
                for (int j = 0; j < 8; j++)
                    mma_f16(acc[t][j], af[cur][t], bf[cur][j]);
        }

        if (++stage == STAGES) stage = 0;
    }

    // epilogue: float2 stores (m16n8 C layout)
    #pragma unroll
    for (int t = 0; t < 2; t++) {
        const int r0 = m_base + warp_m * 32 + t * 16 + grp;
        #pragma unroll
        for (int j = 0; j < 8; j++) {
            const int cg = n_base + warp_n * 64 + j * 8 + 2 * tig;
            float2 v0 = make_float2(acc[t][j][0], acc[t][j][1]);
            float2 v1 = make_float2(acc[t][j][2], acc[t][j][3]);
            *reinterpret_cast<float2*>(out + (size_t)r0 * NDIM + cg) = v0;
            *reinterpret_cast<float2*>(out + (size_t)(r0 + 8) * NDIM + cg) = v1;
        }
    }
}

// ------------------------------- launch --------------------------------------

extern "C" void kernel_launch(void* const* d_in, const int* in_sizes, int n_in,
                              void* d_out, int out_size) {
    const float* A = (const float*)d_in[0];   // [8,1024,4096] == [8192,4096]
    const float* W = (const float*)d_in[1];   // [4096,4096] (N,K)
    float* out = (float*)d_out;               // [8192,4096]
    (void)in_sizes; (void)n_in; (void)out_size;

    cudaFuncSetAttribute(gemm_kernel,
                         cudaFuncAttributeMaxDynamicSharedMemorySize, SMEM_TOTAL);

    prepass_kernel<<<1184, 256>>>(A, W);

    dim3 grid(NDIM / BN, MTOT / BM);   // (32, 64) = 2048 CTAs
    gemm_kernel<<<grid, 256, SMEM_TOTAL>>>(out);
}

// round 12
// speedup vs baseline: 1.1245x; 1.1245x over previous
#include <cuda_runtime.h>
#include <cuda_fp16.h>
#include <cstdint>

// ---------------------------------------------------------------------------
// C[8192,4096] = A[8192,4096] * W[4096,4096]^T  (fp32 in/out)
// R12: fp16 m16n8k16 GEMM. vs R10: 4 CTAs/SM of 128 threads (1 warp per
// CTA per SMSP) -> maximal barrier-domain decoupling; when one CTA syncs,
// 3 other warps per SMSP keep the tensor pipe busy.
// BM=128, BN=64, BK=64, warp tile 32x64, 2-stage cp.async, ldmatrix.x4.
// ---------------------------------------------------------------------------

#define MTOT 8192
#define KDIM 4096
#define NDIM 4096

#define BM 128
#define BN 64
#define BK 64
#define KITERS (KDIM / BK)        // 64
#define STAGES 2

// fp16 smem rows: 64 fp16 = 128B data + 16B pad = 144B stride.
// 144 mod 128 walks {0,16,...,112} over 8 rows -> ldmatrix conflict-free.
#define ROWB 144
#define A_OFF 0
#define B_OFF (BM * ROWB)                  // 18432
#define STAGE_BYTES ((BM + BN) * ROWB)     // 27648
#define SMEM_TOTAL (STAGES * STAGE_BYTES)  // 55296  (x4 CTAs = 221184/SM)

// fp16 scratch copies (device globals: allowed, no allocation)
__device__ __half g_Ah[(size_t)MTOT * KDIM];
__device__ __half g_Wh[(size_t)NDIM * KDIM];

// ------------------------------- helpers -----------------------------------

__device__ __forceinline__ uint32_t smem_u32(const void* p) {
    uint32_t a;
    asm("{ .reg .u64 t; cvta.to.shared.u64 t, %1; cvt.u32.u64 %0, t; }"
        : "=r"(a) : "l"(p));
    return a;
}

__device__ __forceinline__ void cp_async16(uint32_t dst, const void* src) {
    asm volatile("cp.async.cg.shared.global [%0], [%1], 16;\n"
                 :: "r"(dst), "l"(src) : "memory");
}
__device__ __forceinline__ void cp_commit() {
    asm volatile("cp.async.commit_group;\n" ::: "memory");
}
__device__ __forceinline__ void cp_wait1() {
    asm volatile("cp.async.wait_group 1;\n" ::: "memory");
}

__device__ __forceinline__ void ldsm_x4(uint32_t& r0, uint32_t& r1,
                                        uint32_t& r2, uint32_t& r3,
                                        uint32_t addr) {
    asm volatile("ldmatrix.sync.aligned.m8n8.x4.shared.b16 {%0,%1,%2,%3}, [%4];"
                 : "=r"(r0), "=r"(r1), "=r"(r2), "=r"(r3) : "r"(addr));
}

__device__ __forceinline__ void mma_f16(float* c, const uint32_t* a,
                                        const uint32_t* b) {
    asm volatile(
        "mma.sync.aligned.m16n8k16.row.col.f32.f16.f16.f32 "
        "{%0,%1,%2,%3}, {%4,%5,%6,%7}, {%8,%9}, {%0,%1,%2,%3};"
        : "+f"(c[0]), "+f"(c[1]), "+f"(c[2]), "+f"(c[3])
        : "r"(a[0]), "r"(a[1]), "r"(a[2]), "r"(a[3]),
          "r"(b[0]), "r"(b[1]));
}

// ------------------------------- prepass ------------------------------------

__global__ void __launch_bounds__(256) prepass_kernel(const float* __restrict__ A,
                                                      const float* __restrict__ W) {
    const long long nA = (long long)MTOT * KDIM / 4;
    const long long nW = (long long)NDIM * KDIM / 4;
    const long long stride = (long long)gridDim.x * blockDim.x;
    for (long long i = (long long)blockIdx.x * blockDim.x + threadIdx.x;
         i < nA + nW; i += stride) {
        const float4* src;
        __half* dst;
        long long j;
        if (i < nA) { src = (const float4*)A; dst = g_Ah; j = i; }
        else        { src = (const float4*)W; dst = g_Wh; j = i - nA; }
        float4 v = src[j];
        __half2* p = (__half2*)(dst + 4 * j);
        p[0] = __floats2half2_rn(v.x, v.y);
        p[1] = __floats2half2_rn(v.z, v.w);
    }
}

// ------------------------------- GEMM ---------------------------------------

__global__ void __launch_bounds__(128, 4) gemm_kernel(float* __restrict__ out) {
    extern __shared__ char smem[];
    const uint32_t sbase = smem_u32(smem);
    const int tid = threadIdx.x;
    const int lane = tid & 31;
    const int wid = tid >> 5;         // 0..3 -> 32-row strip (warp covers all BN)
    const int grp = lane >> 2;
    const int tig = lane & 3;

    const int m_base = blockIdx.y * BM;
    const int n_base = blockIdx.x * BN;

    // --- ldmatrix per-lane base addresses (stage 0) ---
    const int lj = lane >> 3;         // matrix index 0..3
    const int lr = lane & 7;          // row within matrix
    // A: matrix j -> (m-half = j&1, k-half = j>>1)
    const uint32_t a_lane = sbase + A_OFF
        + (uint32_t)((wid * 32 + (lj & 1) * 8 + lr) * ROWB + (lj >> 1) * 16);
    // B: matrix j -> (n-sub = j>>1, k-half = j&1)
    const uint32_t b_lane = sbase + B_OFF
        + (uint32_t)(((lj >> 1) * 8 + lr) * ROWB + (lj & 1) * 16);

    float acc[2][8][4];
    #pragma unroll
    for (int t = 0; t < 2; t++)
        #pragma unroll
        for (int j = 0; j < 8; j++)
            #pragma unroll
            for (int q = 0; q < 4; q++)
                acc[t][j][q] = 0.0f;

    auto produce = [&](int stage, int kb) {
        char* st = smem + stage * STAGE_BYTES;
        const size_t kel = (size_t)kb * BK;
        // A: 128 rows x 8 chunks of 16B = 1024 chunks -> 8 per thread
        #pragma unroll
        for (int j = 0; j < 8; j++) {
            const int c = tid + 128 * j;     // 0..1023
            const int r = c >> 3, ch = c & 7;
            cp_async16(smem_u32(st + A_OFF + r * ROWB + ch * 16),
                       g_Ah + (size_t)(m_base + r) * KDIM + kel + ch * 8);
        }
        // B: 64 rows x 8 chunks = 512 chunks -> 4 per thread
        #pragma unroll
        for (int j = 0; j < 4; j++) {
            const int c = tid + 128 * j;     // 0..511
            const int r = c >> 3, ch = c & 7;
            cp_async16(smem_u32(st + B_OFF + r * ROWB + ch * 16),
                       g_Wh + (size_t)(n_base + r) * KDIM + kel + ch * 8);
        }
    };

    // prologue: fill both stages
    produce(0, 0); cp_commit();
    produce(1, 1); cp_commit();

    for (int it = 0; it < KITERS; ++it) {
        const int stage = it & 1;

        cp_wait1();          // stage `it` resident (stage it+1 may be in flight)
        __syncthreads();     // all threads see it

        const uint32_t so = (uint32_t)(stage * STAGE_BYTES);

        #pragma unroll
        for (int ks = 0; ks < 4; ks++) {      // 4 x k16 = BK 64
            const uint32_t koff = so + ks * 32;   // 16 fp16 = 32 B
            uint32_t a[2][4], b[8][2];
            #pragma unroll
            for (int t = 0; t < 2; t++)
                ldsm_x4(a[t][0], a[t][1], a[t][2], a[t][3],
                        a_lane + koff + (uint32_t)(t * 16 * ROWB));
            #pragma unroll
            for (int p = 0; p < 4; p++)
                ldsm_x4(b[2 * p][0], b[2 * p][1], b[2 * p + 1][0], b[2 * p + 1][1],
                        b_lane + koff + (uint32_t)(p * 16 * ROWB));
            #pragma unroll
            for (int t = 0; t < 2; t++)
                #pragma unroll
                for (int j = 0; j < 8; j++)
                    mma_f16(acc[t][j], a[t], b[j]);
        }

        __syncthreads();     // all reads of stage `it` done; buffer reusable
        if (it + 2 < KITERS) produce(stage, it + 2);
        cp_commit();         // fixed group count per iteration
    }

    // epilogue: float2 stores (m16n8 C layout)
    #pragma unroll
    for (int t = 0; t < 2; t++) {
        const int r0 = m_base + wid * 32 + t * 16 + grp;
        #pragma unroll
        for (int j = 0; j < 8; j++) {
            const int cg = n_base + j * 8 + 2 * tig;
            float2 v0 = make_float2(acc[t][j][0], acc[t][j][1]);
            float2 v1 = make_float2(acc[t][j][2], acc[t][j][3]);
            *reinterpret_cast<float2*>(out + (size_t)r0 * NDIM + cg) = v0;
            *reinterpret_cast<float2*>(out + (size_t)(r0 + 8) * NDIM + cg) = v1;
        }
    }
}

// ------------------------------- launch --------------------------------------

extern "C" void kernel_launch(void* const* d_in, const int* in_sizes, int n_in,
                              void* d_out, int out_size) {
    const float* A = (const float*)d_in[0];   // [8,1024,4096] == [8192,4096]
    const float* W = (const float*)d_in[1];   // [4096,4096] (N,K)
    float* out = (float*)d_out;               // [8192,4096]
    (void)in_sizes; (void)n_in; (void)out_size;

    cudaFuncSetAttribute(gemm_kernel,
                         cudaFuncAttributeMaxDynamicSharedMemorySize, SMEM_TOTAL);

    prepass_kernel<<<1184, 256>>>(A, W);

    dim3 grid(NDIM / BN, MTOT / BM);   // (64, 64) = 4096 CTAs
    gemm_kernel<<<grid, 128, SMEM_TOTAL>>>(out);
}

// round 13
// speedup vs baseline: 1.2417x; 1.1043x over previous
#include <cuda_runtime.h>
#include <cuda_fp16.h>
#include <cstdint>

// ---------------------------------------------------------------------------
// C[8192,4096] = A[8192,4096] * W[4096,4096]^T  (fp32 in/out)
// R13: fp16 m16n8k16 GEMM. vs R12: 3 CTAs/SM x 3-stage ring -> ONE barrier
// per iteration with distance-2 refill overlapping the mma loop; XOR-swizzled
// smem (ROWB=128, no padding) to fit; fragment double-buffer (reg cap 170).
// BM=128, BN=64, BK=64, 128 thr, warp tile 32x64.
// ---------------------------------------------------------------------------

#define MTOT 8192
#define KDIM 4096
#define NDIM 4096

#define BM 128
#define BN 64
#define BK 64
#define KITERS (KDIM / BK)        // 64
#define STAGES 3

// swizzled rows: 64 fp16 = 128B exactly; addr = row*128 + (k16off ^ (row&7)<<4)
#define ROWB 128
#define A_OFF 0
#define B_OFF (BM * ROWB)                  // 16384
#define STAGE_BYTES ((BM + BN) * ROWB)     // 24576
#define SMEM_TOTAL (STAGES * STAGE_BYTES)  // 73728  (x3 CTAs = 221184/SM)

// fp16 scratch copies (device globals: allowed, no allocation)
__device__ __half g_Ah[(size_t)MTOT * KDIM];
__device__ __half g_Wh[(size_t)NDIM * KDIM];

// ------------------------------- helpers -----------------------------------

__device__ __forceinline__ uint32_t smem_u32(const void* p) {
    uint32_t a;
    asm("{ .reg .u64 t; cvta.to.shared.u64 t, %1; cvt.u32.u64 %0, t; }"
        : "=r"(a) : "l"(p));
    return a;
}

__device__ __forceinline__ void cp_async16(uint32_t dst, const void* src) {
    asm volatile("cp.async.cg.shared.global [%0], [%1], 16;\n"
                 :: "r"(dst), "l"(src) : "memory");
}
__device__ __forceinline__ void cp_commit() {
    asm volatile("cp.async.commit_group;\n" ::: "memory");
}
__device__ __forceinline__ void cp_wait1() {
    asm volatile("cp.async.wait_group 1;\n" ::: "memory");
}

__device__ __forceinline__ void ldsm_x4(uint32_t& r0, uint32_t& r1,
                                        uint32_t& r2, uint32_t& r3,
                                        uint32_t addr) {
    asm volatile("ldmatrix.sync.aligned.m8n8.x4.shared.b16 {%0,%1,%2,%3}, [%4];"
                 : "=r"(r0), "=r"(r1), "=r"(r2), "=r"(r3) : "r"(addr));
}

__device__ __forceinline__ void mma_f16(float* c, const uint32_t* a,
                                        const uint32_t* b) {
    asm volatile(
        "mma.sync.aligned.m16n8k16.row.col.f32.f16.f16.f32 "
        "{%0,%1,%2,%3}, {%4,%5,%6,%7}, {%8,%9}, {%0,%1,%2,%3};"
        : "+f"(c[0]), "+f"(c[1]), "+f"(c[2]), "+f"(c[3])
        : "r"(a[0]), "r"(a[1]), "r"(a[2]), "r"(a[3]),
          "r"(b[0]), "r"(b[1]));
}

// ------------------------------- prepass ------------------------------------

__global__ void __launch_bounds__(256) prepass_kernel(const float* __restrict__ A,
                                                      const float* __restrict__ W) {
    const long long nA = (long long)MTOT * KDIM / 4;
    const long long nW = (long long)NDIM * KDIM / 4;
    const long long stride = (long long)gridDim.x * blockDim.x;
    for (long long i = (long long)blockIdx.x * blockDim.x + threadIdx.x;
         i < nA + nW; i += stride) {
        const float4* src;
        __half* dst;
        long long j;
        if (i < nA) { src = (const float4*)A; dst = g_Ah; j = i; }
        else        { src = (const float4*)W; dst = g_Wh; j = i - nA; }
        float4 v = src[j];
        __half2* p = (__half2*)(dst + 4 * j);
        p[0] = __floats2half2_rn(v.x, v.y);
        p[1] = __floats2half2_rn(v.z, v.w);
    }
}

// ------------------------------- GEMM ---------------------------------------

__global__ void __launch_bounds__(128, 3) gemm_kernel(float* __restrict__ out) {
    extern __shared__ char smem[];
    const uint32_t sbase = smem_u32(smem);
    const int tid = threadIdx.x;
    const int lane = tid & 31;
    const int wid = tid >> 5;         // 0..3 -> 32-row strip (warp covers all BN)
    const int grp = lane >> 2;
    const int tig = lane & 3;

    const int m_base = blockIdx.y * BM;
    const int n_base = blockIdx.x * BN;

    // --- ldmatrix per-lane geometry (XOR swizzle; xorv = lane-row低3bit <<4) ---
    const int lj = lane >> 3;         // matrix index 0..3
    const int lr = lane & 7;          // row within 8x8 matrix
    const uint32_t xorv = (uint32_t)(lr << 4);
    // A: matrix j -> (m-half = j&1, k-half = j>>1)
    const int arow = wid * 32 + (lj & 1) * 8 + lr;       // + t*16
    const uint32_t aBase = sbase + A_OFF + (uint32_t)(arow * ROWB);
    const uint32_t aK = (uint32_t)((lj >> 1) * 16);      // + ks*32, ^ xorv
    // B: matrix j -> (n-sub = j>>1, k-half = j&1)
    const int brow = (lj >> 1) * 8 + lr;                 // + p*16
    const uint32_t bBase = sbase + B_OFF + (uint32_t)(brow * ROWB);
    const uint32_t bK = (uint32_t)((lj & 1) * 16);

    // --- producer geometry ---
    const int prow = tid >> 3;        // base row 0..15
    const int pch = tid & 7;          // 16B chunk within 128B row
    const uint32_t pxor = (uint32_t)((pch * 16));        // chunk bytes (pre-xor)

    float acc[2][8][4];
    #pragma unroll
    for (int t = 0; t < 2; t++)
        #pragma unroll
        for (int j = 0; j < 8; j++)
            #pragma unroll
            for (int q = 0; q < 4; q++)
                acc[t][j][q] = 0.0f;

    auto produce = [&](int stage, int kb) {
        const uint32_t st = sbase + (uint32_t)(stage * STAGE_BYTES);
        const size_t kel = (size_t)kb * BK;
        // A: 128 rows x 8 chunks = 1024 chunks -> 8 per thread
        #pragma unroll
        for (int j = 0; j < 8; j++) {
            const int r = prow + 16 * j;
            const uint32_t sw = (uint32_t)(r * ROWB) + (pxor ^ ((uint32_t)(r & 7) << 4));
            cp_async16(st + A_OFF + sw,
                       g_Ah + (size_t)(m_base + r) * KDIM + kel + pch * 8);
        }
        // B: 64 rows x 8 chunks = 512 chunks -> 4 per thread
        #pragma unroll
        for (int j = 0; j < 4; j++) {
            const int r = prow + 16 * j;
            const uint32_t sw = (uint32_t)(r * ROWB) + (pxor ^ ((uint32_t)(r & 7) << 4));
            cp_async16(st + B_OFF + sw,
                       g_Wh + (size_t)(n_base + r) * KDIM + kel + pch * 8);
        }
    };

    // prologue: fill stages 0 and 1
    produce(0, 0); cp_commit();
    produce(1, 1); cp_commit();

    // fragment double buffers
    uint32_t af[2][2][4], bf[2][8][2];

    int stage = 0;
    for (int it = 0; it < KITERS; ++it) {
        cp_wait1();          // stage `it` resident (next stage may be in flight)
        __syncthreads();     // all warps past iter it-1 -> stage (it+2)%3 reusable

        if (it + 2 < KITERS) {
            int ps = stage + 2; if (ps >= STAGES) ps -= STAGES;
            produce(ps, it + 2);          // overlaps the mma loop below
        }
        cp_commit();

        const uint32_t so = (uint32_t)(stage * STAGE_BYTES);

        // load ks=0 fragments into buffer 0
        #pragma unroll
        for (int t = 0; t < 2; t++)
            ldsm_x4(af[0][t][0], af[0][t][1], af[0][t][2], af[0][t][3],
                    aBase + so + (uint32_t)(t * 16 * ROWB) + (aK ^ xorv));
        #pragma unroll
        for (int p = 0; p < 4; p++)
            ldsm_x4(bf[0][2 * p][0], bf[0][2 * p][1],
                    bf[0][2 * p + 1][0], bf[0][2 * p + 1][1],
                    bBase + so + (uint32_t)(p * 16 * ROWB) + (bK ^ xorv));

        #pragma unroll
        for (int ks = 0; ks < 4; ks++) {      // 4 x k16 = BK 64
            const int cur = ks & 1;
            const int nxt = cur ^ 1;
            if (ks < 3) {                      // prefetch ks+1 fragments
                const uint32_t ka = ((uint32_t)((ks + 1) * 32) + aK) ^ xorv;
                const uint32_t kb2 = ((uint32_t)((ks + 1) * 32) + bK) ^ xorv;
                #pragma unroll
                for (int t = 0; t < 2; t++)
                    ldsm_x4(af[nxt][t][0], af[nxt][t][1], af[nxt][t][2], af[nxt][t][3],
                            aBase + so + (uint32_t)(t * 16 * ROWB) + ka);
                #pragma unroll
                for (int p = 0; p < 4; p++)
                    ldsm_x4(bf[nxt][2 * p][0], bf[nxt][2 * p][1],
                            bf[nxt][2 * p + 1][0], bf[nxt][2 * p + 1][1],
                            bBase + so + (uint32_t)(p * 16 * ROWB) + kb2);
            }
            #pragma unroll
            for (int t = 0; t < 2; t++)
                #pragma unroll
                for (int j = 0; j < 8; j++)
                    mma_f16(acc[t][j], af[cur][t], bf[cur][j]);
        }

        if (++stage == STAGES) stage = 0;
    }

    // epilogue: float2 stores (m16n8 C layout)
    #pragma unroll
    for (int t = 0; t < 2; t++) {
        const int r0 = m_base + wid * 32 + t * 16 + grp;
        #pragma unroll
        for (int j = 0; j < 8; j++) {
            const int cg = n_base + j * 8 + 2 * tig;
            float2 v0 = make_float2(acc[t][j][0], acc[t][j][1]);
            float2 v1 = make_float2(acc[t][j][2], acc[t][j][3]);
            *reinterpret_cast<float2*>(out + (size_t)r0 * NDIM + cg) = v0;
            *reinterpret_cast<float2*>(out + (size_t)(r0 + 8) * NDIM + cg) = v1;
        }
    }
}

// ------------------------------- launch --------------------------------------

extern "C" void kernel_launch(void* const* d_in, const int* in_sizes, int n_in,
                              void* d_out, int out_size) {
    const float* A = (const float*)d_in[0];   // [8,1024,4096] == [8192,4096]
    const float* W = (const float*)d_in[1];   // [4096,4096] (N,K)
    float* out = (float*)d_out;               // [8192,4096]
    (void)in_sizes; (void)n_in; (void)out_size;

    cudaFuncSetAttribute(gemm_kernel,
                         cudaFuncAttributeMaxDynamicSharedMemorySize, SMEM_TOTAL);

    prepass_kernel<<<1184, 256>>>(A, W);

    dim3 grid(NDIM / BN, MTOT / BM);   // (64, 64) = 4096 CTAs
    gemm_kernel<<<grid, 128, SMEM_TOTAL>>>(out);
}